// round 10
// baseline (speedup 1.0000x reference)
#include <cuda_runtime.h>
#include <cuda_bf16.h>
#include <cstdint>
#include <math.h>

// Problem shapes (fixed)
#define NX 4096
#define NY 16384
#define CX 128
#define CY 128
#define OD 256
#define KIN 256
#define BIGD 1e30f
#define W_EPS 1e-16f
#define LN_EPS 1e-5f

// Global scratch: W split only
__device__ __nv_bfloat16 g_Wh[OD * KIN];
__device__ __nv_bfloat16 g_Wl[OD * KIN];

// ---------------------------------------------------------------------------
// Helpers (baseline PTX, valid for compute_100)
// ---------------------------------------------------------------------------
static __device__ __forceinline__ uint32_t smem_u32(const void* p) {
    uint32_t a;
    asm("{ .reg .u64 t; cvta.to.shared.u64 t, %1; cvt.u32.u64 %0, t; }"
        : "=r"(a) : "l"(p));
    return a;
}

static __device__ __forceinline__ void ldsm_x4(uint32_t addr, uint32_t* r) {
    asm volatile("ldmatrix.sync.aligned.m8n8.x4.shared.b16 {%0,%1,%2,%3}, [%4];"
                 : "=r"(r[0]), "=r"(r[1]), "=r"(r[2]), "=r"(r[3]) : "r"(addr));
}

static __device__ __forceinline__ void mma_bf16(float* d, const uint32_t* a,
                                                uint32_t b0, uint32_t b1) {
    asm volatile(
        "mma.sync.aligned.m16n8k16.row.col.f32.bf16.bf16.f32 "
        "{%0,%1,%2,%3},{%4,%5,%6,%7},{%8,%9},{%0,%1,%2,%3};"
        : "+f"(d[0]), "+f"(d[1]), "+f"(d[2]), "+f"(d[3])
        : "r"(a[0]), "r"(a[1]), "r"(a[2]), "r"(a[3]), "r"(b0), "r"(b1));
}

static __device__ __forceinline__ void cp_async16(uint32_t dst, const void* src) {
    asm volatile("cp.async.cg.shared.global [%0], [%1], 16;" :: "r"(dst), "l"(src));
}
static __device__ __forceinline__ void cp_commit() {
    asm volatile("cp.async.commit_group;" ::: "memory");
}
template <int N>
static __device__ __forceinline__ void cp_wait() {
    asm volatile("cp.async.wait_group %0;" :: "n"(N) : "memory");
}

// Fast hi/lo bf16 split of a float pair
static __device__ __forceinline__ void split_pair(float v0, float v1,
                                                  uint32_t& hp, uint32_t& lp) {
    uint32_t u0 = __float_as_uint(v0), u1 = __float_as_uint(v1);
    asm("prmt.b32 %0, %1, %2, 0x7632;" : "=r"(hp) : "r"(u0), "r"(u1));
    float h0 = __uint_as_float(u0 & 0xFFFF0000u);
    float h1 = __uint_as_float(u1 & 0xFFFF0000u);
    float l0 = v0 - h0, l1 = v1 - h1;
    asm("cvt.rn.bf16x2.f32 %0, %1, %2;" : "=r"(lp) : "f"(l1), "f"(l0));
}

// Branchless top-3 insert (distance only)
#define BINSERT(dd, jj)                                                         \
    do {                                                                        \
        float _d = (dd); int _j = (jj);                                         \
        bool lt0 = _d < d0;                                                     \
        bool lt1 = _d < d1;                                                     \
        bool lt2 = _d < d2v;                                                    \
        d2v = lt1 ? d1 : (lt2 ? _d : d2v); i2 = lt1 ? i1 : (lt2 ? _j : i2);     \
        d1  = lt0 ? d0 : (lt1 ? _d : d1);  i1 = lt0 ? i0 : (lt1 ? _j : i1);     \
        d0  = lt0 ? _d : d0;               i0 = lt0 ? _j : i0;                  \
    } while (0)

// ---------------------------------------------------------------------------
// Kernel 0: W split (packed u32 stores)
// ---------------------------------------------------------------------------
__global__ __launch_bounds__(256)
void wsplit_kernel(const float* __restrict__ W) {
    int base = blockIdx.x * (256 * 4) + threadIdx.x;
    uint32_t* wh = (uint32_t*)g_Wh;
    uint32_t* wl = (uint32_t*)g_Wl;
#pragma unroll
    for (int i = 0; i < 4; i++) {
        int p = base + i * 256;
        float2 v = *(const float2*)&W[p * 2];
        split_pair(v.x, v.y, wh[p], wl[p]);
    }
}

// ---------------------------------------------------------------------------
// Kernel 1 (FUSED): KNN+interp -> smem A -> bf16 hi/lo mma GEMM -> LN+ReLU
// Per CTA: 64 query rows x 256 out cols. 256 threads = 8 warps (2m x 4n),
// warp tile 32m x 64n. K = 256 in 8 phases of 32 (single B buffer).
// 2 CTAs/SM co-resident: one CTA's KNN (ALU) overlaps the other's GEMM
// (tensor); 256 CTAs use all 148 SMs.
//
// SMEM (106 KB dynamic):
//   A_hi [64][528B] @ 0      (33792)
//   A_lo           @ 33792   (33792)
//   POS/B region   @ 67584   (40960): pos cache during KNN (<=2560 pts),
//     then B phase buffer {BH@+0, BL@+20480}, then LN stats
// ---------------------------------------------------------------------------
#define SROW 528
#define A_HI 0
#define A_LO 33792
#define POSB 67584
#define BSTR 80
#define BLOF 20480
#define G_TOTAL 108544
#define MAXP 2560

__global__ __launch_bounds__(256, 2)
void fused_kernel(const float* __restrict__ pos_x,
                  const float* __restrict__ xfeat,
                  const int*   __restrict__ batch_x,
                  const float* __restrict__ pos_y,
                  const float* __restrict__ yfeat,
                  const int*   __restrict__ batch_y,
                  const float* __restrict__ gamma,
                  const float* __restrict__ beta,
                  float* __restrict__ out)
{
    extern __shared__ char smem[];
    const uint32_t sb = smem_u32(smem);
    __shared__ int sbounds[9];

    const int tid  = threadIdx.x;
    const int wid  = tid >> 5;
    const int lane = tid & 31;
    const int rowBase = blockIdx.x * 64;

    // ---- batch boundaries ----
    if (tid < 9) {
        int t = tid;
        int lo = 0, hi = NX;
        while (lo < hi) { int m = (lo + hi) >> 1; if (batch_x[m] < t) lo = m + 1; else hi = m; }
        sbounds[t] = lo;
    }
    __syncthreads();

    const int bmin = batch_y[rowBase];
    const int bmax = batch_y[rowBase + 63];
    const int s0   = sbounds[bmin];
    const int e1   = sbounds[bmax + 1];
    const int n    = e1 - s0;
    const bool inSmem = (n <= MAXP);

    // ---- stage pos segment (x,y,z,|p|^2) into the B region ----
    if (inSmem) {
        for (int i = tid; i < n; i += 256) {
            int j = s0 + i;
            float x = pos_x[j * 3 + 0];
            float y = pos_x[j * 3 + 1];
            float z = pos_x[j * 3 + 2];
            *(float4*)(smem + POSB + (uint32_t)i * 16) =
                make_float4(x, y, z, x * x + y * y + z * z);
        }
    }
    __syncthreads();

    // ---- KNN + interp: each warp handles 8 query rows ----
#pragma unroll 1
    for (int q = 0; q < 8; q++) {
        const int yloc = wid * 8 + q;
        const int yi   = rowBase + yloc;

        const float py0 = pos_y[yi * 3 + 0];
        const float py1 = pos_y[yi * 3 + 1];
        const float py2 = pos_y[yi * 3 + 2];
        const float ny2 = py0 * py0 + py1 * py1 + py2 * py2;
        const int b = batch_y[yi];
        const int s = sbounds[b];
        const int e = sbounds[b + 1];

        float d0 = BIGD, d1 = BIGD, d2v = BIGD;
        int   i0 = 0,    i1 = 0,    i2 = 0;

        if (inSmem) {
            const int ls = s - s0, le = e - s0;
            for (int jl = ls + lane; jl < le; jl += 32) {
                float4 p = *(const float4*)(smem + POSB + (uint32_t)jl * 16);
                float dot = py0 * p.x + py1 * p.y + py2 * p.z;
                float d = fmaxf(ny2 + p.w - 2.0f * dot, 0.0f);
                BINSERT(d, s0 + jl);
            }
        } else {
            for (int j = s + lane; j < e; j += 32) {
                float px0 = pos_x[j * 3 + 0];
                float px1 = pos_x[j * 3 + 1];
                float px2 = pos_x[j * 3 + 2];
                float nx2 = px0 * px0 + px1 * px1 + px2 * px2;
                float dot = py0 * px0 + py1 * px1 + py2 * px2;
                float d = fmaxf(ny2 + nx2 - 2.0f * dot, 0.0f);
                BINSERT(d, j);
            }
        }

        for (int off = 16; off; off >>= 1) {
            float od0 = __shfl_xor_sync(0xffffffffu, d0,  off);
            float od1 = __shfl_xor_sync(0xffffffffu, d1,  off);
            float od2 = __shfl_xor_sync(0xffffffffu, d2v, off);
            int   oi0 = __shfl_xor_sync(0xffffffffu, i0,  off);
            int   oi1 = __shfl_xor_sync(0xffffffffu, i1,  off);
            int   oi2 = __shfl_xor_sync(0xffffffffu, i2,  off);
            BINSERT(od0, oi0);
            BINSERT(od1, oi1);
            BINSERT(od2, oi2);
        }

        const float w0 = 1.0f / fmaxf(d0,  W_EPS);
        const float w1 = 1.0f / fmaxf(d1,  W_EPS);
        const float w2 = 1.0f / fmaxf(d2v, W_EPS);
        const float inv_wsum = 1.0f / (w0 + w1 + w2);

        const float* f0 = xfeat + (size_t)i0 * CX;
        const float* f1 = xfeat + (size_t)i1 * CX;
        const float* f2 = xfeat + (size_t)i2 * CX;
        const float* fy = yfeat + (size_t)yi * CY;

        const int c = lane * 4;
        float4 a0 = *(const float4*)&f0[c];
        float4 a1 = *(const float4*)&f1[c];
        float4 a2 = *(const float4*)&f2[c];
        float4 ay = *(const float4*)&fy[c];
        float v0 = (w0 * a0.x + w1 * a1.x + w2 * a2.x) * inv_wsum;
        float v1 = (w0 * a0.y + w1 * a1.y + w2 * a2.y) * inv_wsum;
        float v2 = (w0 * a0.z + w1 * a1.z + w2 * a2.z) * inv_wsum;
        float v3 = (w0 * a0.w + w1 * a1.w + w2 * a2.w) * inv_wsum;

        const uint32_t arow = (uint32_t)(yloc * SROW + lane * 8);
        uint2 hp, lp;
        split_pair(v0, v1, hp.x, lp.x);
        split_pair(v2, v3, hp.y, lp.y);
        *(uint2*)(smem + A_HI + arow) = hp;
        *(uint2*)(smem + A_LO + arow) = lp;
        split_pair(ay.x, ay.y, hp.x, lp.x);
        split_pair(ay.z, ay.w, hp.y, lp.y);
        *(uint2*)(smem + A_HI + arow + 256) = hp;   // y-half: k = 128 + lane*4
        *(uint2*)(smem + A_LO + arow + 256) = lp;
    }
    __syncthreads();                  // A complete; pos region free for B

    // ---- B phase loader (K=32 per phase, single buffer) ----
    auto load_B = [&](int p) {
        const int kof = p * 32;
#pragma unroll
        for (int i = 0; i < 4; i++) {
            int idx = tid + i * 256;               // 0..1023
            int r = idx >> 2, kc = idx & 3;
            const size_t gs = (size_t)r * KIN + kof + kc * 8;
            uint32_t off = (uint32_t)(r * BSTR + kc * 16);
            cp_async16(sb + POSB + off, &g_Wh[gs]);
            cp_async16(sb + POSB + BLOF + off, &g_Wl[gs]);
        }
        cp_commit();
    };

    load_B(0);

    // ---- GEMM mainloop ----
    const int g   = lane >> 2;
    const int tig = lane & 3;
    const int mw  = (wid >> 2) * 32;               // warp row base (0/32)
    const int nw  = wid & 3;                       // warp col base = nw*64

    const int quad  = lane >> 3;
    const int lrow  = lane & 7;
    const int aRow  = (quad & 1) * 8 + lrow;
    const int aKoff = (quad >> 1) * 8;
    const int bRow  = ((lane >> 4) * 8) + lrow;
    const int bKoff = ((lane >> 3) & 1) * 8;
    const uint32_t offB = (uint32_t)((nw * 64 + bRow) * BSTR + bKoff * 2);
    const uint32_t aCol = (uint32_t)((mw + aRow) * SROW + aKoff * 2);

    float acc[2][8][4];
#pragma unroll
    for (int mt = 0; mt < 2; mt++)
#pragma unroll
        for (int nt = 0; nt < 8; nt++)
#pragma unroll
            for (int j = 0; j < 4; j++) acc[mt][nt][j] = 0.f;

#pragma unroll 1
    for (int p = 0; p < 8; p++) {
        cp_wait<0>();
        __syncthreads();

        const uint32_t bB = sb + POSB + offB;
        const uint32_t aB = sb + A_HI + aCol + (uint32_t)(p * 64);

#pragma unroll
        for (int ks = 0; ks < 2; ks++) {
            const uint32_t kb = (uint32_t)(ks * 32);
            uint32_t Bh[16], Bl[16];
#pragma unroll
            for (int i = 0; i < 4; i++) {
                uint32_t ba = bB + (uint32_t)(i * 16 * BSTR) + kb;
                ldsm_x4(ba, &Bh[i * 4]);
                ldsm_x4(ba + BLOF, &Bl[i * 4]);
            }
#pragma unroll
            for (int mt = 0; mt < 2; mt++) {
                uint32_t Ah[4], Al[4];
                const uint32_t aa = aB + (uint32_t)(mt * 16 * SROW) + kb;
                ldsm_x4(aa, Ah);
                ldsm_x4(aa + (A_LO - A_HI), Al);
                // term-major: RAW distance 8 between touches of same acc
#pragma unroll
                for (int nt = 0; nt < 8; nt++)
                    mma_bf16(acc[mt][nt], Ah, Bh[2 * nt], Bh[2 * nt + 1]);
#pragma unroll
                for (int nt = 0; nt < 8; nt++)
                    mma_bf16(acc[mt][nt], Al, Bh[2 * nt], Bh[2 * nt + 1]);
#pragma unroll
                for (int nt = 0; nt < 8; nt++)
                    mma_bf16(acc[mt][nt], Ah, Bl[2 * nt], Bl[2 * nt + 1]);
            }
        }
        __syncthreads();
        if (p < 7) load_B(p + 1);
    }

    // ---- LayerNorm stats (overlay B region) ----
    float* sSum = (float*)(smem + POSB);           // [64][4]
    float* sSq  = sSum + 256;
    float* sMu  = sSq + 256;
    float* sRs  = sMu + 64;

#pragma unroll
    for (int mt = 0; mt < 2; mt++)
#pragma unroll
        for (int half = 0; half < 2; half++) {
            float s = 0.f, q = 0.f;
#pragma unroll
            for (int nt = 0; nt < 8; nt++)
#pragma unroll
                for (int j = 0; j < 2; j++) {
                    float v = acc[mt][nt][half * 2 + j];
                    s += v; q += v * v;
                }
            s += __shfl_xor_sync(0xffffffffu, s, 1);
            q += __shfl_xor_sync(0xffffffffu, q, 1);
            s += __shfl_xor_sync(0xffffffffu, s, 2);
            q += __shfl_xor_sync(0xffffffffu, q, 2);
            if (tig == 0) {
                int row = mw + mt * 16 + half * 8 + g;
                sSum[row * 4 + nw] = s;
                sSq[row * 4 + nw]  = q;
            }
        }
    __syncthreads();

    if (tid < 64) {
        float s = sSum[tid * 4] + sSum[tid * 4 + 1] + sSum[tid * 4 + 2] + sSum[tid * 4 + 3];
        float q = sSq[tid * 4] + sSq[tid * 4 + 1] + sSq[tid * 4 + 2] + sSq[tid * 4 + 3];
        float mu = s * (1.0f / OD);
        float var = fmaxf(q * (1.0f / OD) - mu * mu, 0.0f);
        sMu[tid] = mu;
        sRs[tid] = rsqrtf(var + LN_EPS);
    }
    __syncthreads();

    // ---- normalize + affine + ReLU + store ----
#pragma unroll
    for (int mt = 0; mt < 2; mt++)
#pragma unroll
        for (int half = 0; half < 2; half++) {
            int row = mw + mt * 16 + half * 8 + g;
            float mu = sMu[row];
            float rs = sRs[row];
            float* orow = out + (size_t)(rowBase + row) * OD;
#pragma unroll
            for (int nt = 0; nt < 8; nt++) {
                int col = nw * 64 + nt * 8 + tig * 2;
                float2 gb0 = *(const float2*)&gamma[col];
                float2 bb0 = *(const float2*)&beta[col];
                float v0 = acc[mt][nt][half * 2 + 0];
                float v1 = acc[mt][nt][half * 2 + 1];
                float2 r2;
                r2.x = fmaxf((v0 - mu) * rs * gb0.x + bb0.x, 0.0f);
                r2.y = fmaxf((v1 - mu) * rs * gb0.y + bb0.y, 0.0f);
                *(float2*)&orow[col] = r2;
            }
        }
}

// ---------------------------------------------------------------------------
extern "C" void kernel_launch(void* const* d_in, const int* in_sizes, int n_in,
                              void* d_out, int out_size)
{
    const float* pos_x   = (const float*)d_in[0];
    const float* xfeat   = (const float*)d_in[1];
    const int*   batch_x = (const int*)  d_in[2];
    const float* pos_y   = (const float*)d_in[3];
    const float* yfeat   = (const float*)d_in[4];
    const int*   batch_y = (const int*)  d_in[5];
    const float* W       = (const float*)d_in[6];
    const float* gamma   = (const float*)d_in[7];
    const float* beta    = (const float*)d_in[8];
    float* out = (float*)d_out;

    wsplit_kernel<<<32, 256>>>(W);

    cudaFuncSetAttribute(fused_kernel,
                         cudaFuncAttributeMaxDynamicSharedMemorySize, G_TOTAL);
    fused_kernel<<<NY / 64, 256, G_TOTAL>>>(pos_x, xfeat, batch_x, pos_y,
                                            yfeat, batch_y, gamma, beta, out);
}